// round 8
// baseline (speedup 1.0000x reference)
#include <cuda_runtime.h>
#include <cuda_fp16.h>
#include <cstdint>

#define M_DIM 8192
#define N_DIM 4096
#define K_DIM 4096

#define BM 128
#define BN 128
#define BK 64
#define STAGES 3
#define KTILES (K_DIM / BK)

// per-stage smem: A 128x64 f16 (16KB) + B 128x64 f16 (16KB) = 32KB; 3 stages = 96KB
#define STAGE_BYTES 32768
#define B_REL 16384
#define SMEM_TOTAL (STAGES * STAGE_BYTES)

// Scratch (static device arrays: allowed; cudaMalloc: not)
__device__ __half g_xh[(size_t)M_DIM * K_DIM];   // 64 MB: x in fp16
__device__ __half g_ws[(size_t)N_DIM * K_DIM];   // 32 MB: ternary sign pattern in fp16
__device__ float  g_absum;

// ---------------- prep kernels ----------------

__global__ void zero_sum_kernel() { g_absum = 0.0f; }

__global__ void abs_sum_kernel(const float* __restrict__ w) {
    const int n4 = (N_DIM * K_DIM) / 4;
    float s = 0.f;
    const float4* w4 = (const float4*)w;
    for (int j = blockIdx.x * blockDim.x + threadIdx.x; j < n4; j += gridDim.x * blockDim.x) {
        float4 v = w4[j];
        s += fabsf(v.x) + fabsf(v.y) + fabsf(v.z) + fabsf(v.w);
    }
#pragma unroll
    for (int o = 16; o; o >>= 1) s += __shfl_xor_sync(0xffffffffu, s, o);
    __shared__ float red[8];
    int lane = threadIdx.x & 31, wid = threadIdx.x >> 5;
    if (lane == 0) red[wid] = s;
    __syncthreads();
    if (wid == 0) {
        s = (lane < 8) ? red[lane] : 0.f;
#pragma unroll
        for (int o = 4; o; o >>= 1) s += __shfl_xor_sync(0xffffffffu, s, o);
        if (lane == 0) atomicAdd(&g_absum, s);
    }
}

__global__ void quantize_w_kernel(const float* __restrict__ w) {
    const float t = 0.5f * g_absum * (1.0f / ((float)N_DIM * (float)K_DIM));
    size_t i = ((size_t)blockIdx.x * blockDim.x + threadIdx.x) * 8;
    float4 v0 = *(const float4*)(w + i);
    float4 v1 = *(const float4*)(w + i + 4);
    float f[8] = {v0.x, v0.y, v0.z, v0.w, v1.x, v1.y, v1.z, v1.w};
    __half h[8];
#pragma unroll
    for (int j = 0; j < 8; ++j)
        h[j] = __float2half_rn(f[j] > t ? 1.0f : (f[j] < -t ? -1.0f : 0.0f));
    *(uint4*)(g_ws + i) = *(const uint4*)h;
}

__global__ void convert_x_kernel(const float* __restrict__ x) {
    size_t i = ((size_t)blockIdx.x * blockDim.x + threadIdx.x) * 8;
    float4 v0 = *(const float4*)(x + i);
    float4 v1 = *(const float4*)(x + i + 4);
    float f[8] = {v0.x, v0.y, v0.z, v0.w, v1.x, v1.y, v1.z, v1.w};
    __half h[8];
#pragma unroll
    for (int j = 0; j < 8; ++j) h[j] = __float2half_rn(f[j]);
    *(uint4*)(g_xh + i) = *(const uint4*)h;
}

// ---------------- GEMM ----------------

__device__ __forceinline__ uint32_t smem_u32(const void* p) {
    return (uint32_t)__cvta_generic_to_shared(p);
}

__global__ __launch_bounds__(128, 2) void ternary_gemm_kernel(float* __restrict__ out) {
    extern __shared__ char smem[];
    const uint32_t sbase = smem_u32(smem);

    const int tid  = threadIdx.x;
    const int lane = tid & 31;
    const int warp = tid >> 5;          // 4 warps
    const int wm = warp >> 1;           // 2 warps along M (64 rows each)
    const int wn = warp & 1;            // 2 warps along N (64 cols each)
    const int bm = blockIdx.y * BM;
    const int bn = blockIdx.x * BN;

    float facc[4][8][4];                // fp32 running sums (64x64 warp tile)
#pragma unroll
    for (int i = 0; i < 4; ++i)
#pragma unroll
        for (int j = 0; j < 8; ++j)
#pragma unroll
            for (int k = 0; k < 4; ++k) facc[i][j][k] = 0.f;

    uint32_t hacc[4][8][2];             // fp16x2 chunk accumulators
#pragma unroll
    for (int i = 0; i < 4; ++i)
#pragma unroll
        for (int j = 0; j < 8; ++j) { hacc[i][j][0] = 0u; hacc[i][j][1] = 0u; }

    // cp.async: 128 threads; A and B each 1024 16B-chunks -> 8 per thread each
    auto load_tile = [&](int kt) {
        const uint32_t abase = sbase + (kt % STAGES) * STAGE_BYTES;
        const uint32_t bbase = abase + B_REL;
        const __half* gA = g_xh + (size_t)bm * K_DIM + (size_t)kt * BK;
        const __half* gB = g_ws + (size_t)bn * K_DIM + (size_t)kt * BK;
#pragma unroll
        for (int i = 0; i < 8; ++i) {
            const int idx = tid + i * 128;            // 0..1023
            const int r = idx >> 3;                   // row 0..127
            const int c = idx & 7;
            const uint32_t sw = ((uint32_t)((c ^ r) & 7)) << 4;
            asm volatile("cp.async.cg.shared.global [%0], [%1], 16;"
                         :: "r"(abase + r * 128 + sw),
                            "l"((const char*)(gA + (size_t)r * K_DIM) + c * 16));
            asm volatile("cp.async.cg.shared.global [%0], [%1], 16;"
                         :: "r"(bbase + r * 128 + sw),
                            "l"((const char*)(gB + (size_t)r * K_DIM) + c * 16));
        }
        asm volatile("cp.async.commit_group;");
    };

    auto promote = [&]() {
#pragma unroll
        for (int mt = 0; mt < 4; ++mt)
#pragma unroll
            for (int nt = 0; nt < 8; ++nt) {
                float2 t0 = __half22float2(*(const __half2*)&hacc[mt][nt][0]);
                float2 t1 = __half22float2(*(const __half2*)&hacc[mt][nt][1]);
                facc[mt][nt][0] += t0.x;
                facc[mt][nt][1] += t0.y;
                facc[mt][nt][2] += t1.x;
                facc[mt][nt][3] += t1.y;
                hacc[mt][nt][0] = 0u;
                hacc[mt][nt][1] = 0u;
            }
    };

    auto compute_tile = [&](int kt) {
        const uint32_t abase = sbase + (kt % STAGES) * STAGE_BYTES;
        const uint32_t bbase = abase + B_REL;
#pragma unroll
        for (int ks = 0; ks < 4; ++ks) {
            uint32_t a[4][4];
            uint32_t b[4][4];
            // A: 4 x4-ldmatrix (m16 x k16 tiles)
            {
                const int ch = ks * 2 + (lane >> 4);
#pragma unroll
                for (int mt = 0; mt < 4; ++mt) {
                    const int rr = wm * 64 + mt * 16 + (lane & 15);
                    const uint32_t addr = abase + rr * 128 + (((uint32_t)(ch ^ (rr & 7))) << 4);
                    asm volatile("ldmatrix.sync.aligned.m8n8.x4.shared.b16 {%0,%1,%2,%3}, [%4];"
                                 : "=r"(a[mt][0]), "=r"(a[mt][1]), "=r"(a[mt][2]), "=r"(a[mt][3])
                                 : "r"(addr));
                }
            }
            // B: 4 x4-ldmatrix, each covers 2 n8-tiles (16 B-rows x k16)
            {
                const int ch = ks * 2 + ((lane >> 3) & 1);
#pragma unroll
                for (int p = 0; p < 4; ++p) {
                    const int rr = wn * 64 + p * 16 + (lane & 7) + ((lane >> 4) * 8);
                    const uint32_t addr = bbase + rr * 128 + (((uint32_t)(ch ^ (rr & 7))) << 4);
                    asm volatile("ldmatrix.sync.aligned.m8n8.x4.shared.b16 {%0,%1,%2,%3}, [%4];"
                                 : "=r"(b[p][0]), "=r"(b[p][1]), "=r"(b[p][2]), "=r"(b[p][3])
                                 : "r"(addr));
                }
            }
#pragma unroll
            for (int mt = 0; mt < 4; ++mt)
#pragma unroll
                for (int nt = 0; nt < 8; ++nt) {
                    const int p = nt >> 1, h = (nt & 1) * 2;
                    asm volatile("mma.sync.aligned.m16n8k16.row.col.f16.f16.f16.f16 "
                                 "{%0,%1}, {%2,%3,%4,%5}, {%6,%7}, {%0,%1};"
                                 : "+r"(hacc[mt][nt][0]), "+r"(hacc[mt][nt][1])
                                 : "r"(a[mt][0]), "r"(a[mt][1]), "r"(a[mt][2]), "r"(a[mt][3]),
                                   "r"(b[p][h]), "r"(b[p][h + 1]));
                }
            if (ks & 1) promote();      // fp32 promotion every K=32
        }
    };

    load_tile(0);
    load_tile(1);

    for (int kt = 0; kt < KTILES; ++kt) {
        asm volatile("cp.async.wait_group %0;" :: "n"(1));
        __syncthreads();                 // stage kt ready; all warps done reading stage kt-1
        if (kt + 2 < KTILES) load_tile(kt + 2);
        compute_tile(kt);
    }

    // epilogue
    const float alpha = g_absum * (1.0f / ((float)N_DIM * (float)K_DIM));
    const int row0 = bm + wm * 64 + (lane >> 2);
    const int col0 = bn + wn * 64 + (lane & 3) * 2;
#pragma unroll
    for (int mt = 0; mt < 4; ++mt) {
        float* o0 = out + (size_t)(row0 + mt * 16) * N_DIM + col0;
        float* o1 = o0 + (size_t)8 * N_DIM;
#pragma unroll
        for (int nt = 0; nt < 8; ++nt) {
            *(float2*)(o0 + nt * 8) = make_float2(alpha * facc[mt][nt][0], alpha * facc[mt][nt][1]);
            *(float2*)(o1 + nt * 8) = make_float2(alpha * facc[mt][nt][2], alpha * facc[mt][nt][3]);
        }
    }
}

// ---------------- launch ----------------

extern "C" void kernel_launch(void* const* d_in, const int* in_sizes, int n_in,
                              void* d_out, int out_size) {
    const float* x = (const float*)d_in[0];
    const float* w = (const float*)d_in[1];
    if (n_in >= 2 && in_sizes[0] < in_sizes[1]) {  // defensive: x is the bigger tensor
        const float* t = x; x = w; w = t;
    }
    float* out = (float*)d_out;

    cudaFuncSetAttribute(ternary_gemm_kernel,
                         cudaFuncAttributeMaxDynamicSharedMemorySize, SMEM_TOTAL);

    zero_sum_kernel<<<1, 1>>>();
    abs_sum_kernel<<<2048, 256>>>(w);
    quantize_w_kernel<<<(N_DIM * (size_t)K_DIM / 8) / 256, 256>>>(w);
    convert_x_kernel<<<((size_t)M_DIM * K_DIM / 8) / 256, 256>>>(x);

    dim3 grid(N_DIM / BN, M_DIM / BM);
    ternary_gemm_kernel<<<grid, 128, SMEM_TOTAL>>>(out);
}

// round 9
// speedup vs baseline: 2.4122x; 2.4122x over previous
#include <cuda_runtime.h>
#include <cuda_fp16.h>
#include <cstdint>

#define M_DIM 8192
#define N_DIM 4096
#define K_DIM 4096

#define BM 128
#define BN 128
#define BK 64
#define STAGES 3
#define KTILES (K_DIM / BK)

// per-stage smem: A 128x64 f16 (16KB) + B 128x64 f16 (16KB) = 32KB; 3 stages = 96KB
#define STAGE_BYTES 32768
#define B_REL 16384
#define SMEM_TOTAL (STAGES * STAGE_BYTES)

// Scratch (static device arrays: allowed; cudaMalloc: not)
__device__ __half g_xh[(size_t)M_DIM * K_DIM];   // 64 MB: x in fp16
__device__ __half g_ws[(size_t)N_DIM * K_DIM];   // 32 MB: ternary sign pattern in fp16
__device__ float  g_absum;

// ---------------- prep kernels ----------------

__global__ void zero_sum_kernel() { g_absum = 0.0f; }

__global__ void abs_sum_kernel(const float* __restrict__ w) {
    const int n4 = (N_DIM * K_DIM) / 4;
    float s = 0.f;
    const float4* w4 = (const float4*)w;
    for (int j = blockIdx.x * blockDim.x + threadIdx.x; j < n4; j += gridDim.x * blockDim.x) {
        float4 v = w4[j];
        s += fabsf(v.x) + fabsf(v.y) + fabsf(v.z) + fabsf(v.w);
    }
#pragma unroll
    for (int o = 16; o; o >>= 1) s += __shfl_xor_sync(0xffffffffu, s, o);
    __shared__ float red[8];
    int lane = threadIdx.x & 31, wid = threadIdx.x >> 5;
    if (lane == 0) red[wid] = s;
    __syncthreads();
    if (wid == 0) {
        s = (lane < 8) ? red[lane] : 0.f;
#pragma unroll
        for (int o = 4; o; o >>= 1) s += __shfl_xor_sync(0xffffffffu, s, o);
        if (lane == 0) atomicAdd(&g_absum, s);
    }
}

__global__ void quantize_w_kernel(const float* __restrict__ w) {
    const float t = 0.5f * g_absum * (1.0f / ((float)N_DIM * (float)K_DIM));
    size_t i = ((size_t)blockIdx.x * blockDim.x + threadIdx.x) * 8;
    float4 v0 = *(const float4*)(w + i);
    float4 v1 = *(const float4*)(w + i + 4);
    float f[8] = {v0.x, v0.y, v0.z, v0.w, v1.x, v1.y, v1.z, v1.w};
    __half h[8];
#pragma unroll
    for (int j = 0; j < 8; ++j)
        h[j] = __float2half_rn(f[j] > t ? 1.0f : (f[j] < -t ? -1.0f : 0.0f));
    *(uint4*)(g_ws + i) = *(const uint4*)h;
}

__global__ void convert_x_kernel(const float* __restrict__ x) {
    size_t i = ((size_t)blockIdx.x * blockDim.x + threadIdx.x) * 8;
    float4 v0 = *(const float4*)(x + i);
    float4 v1 = *(const float4*)(x + i + 4);
    float f[8] = {v0.x, v0.y, v0.z, v0.w, v1.x, v1.y, v1.z, v1.w};
    __half h[8];
#pragma unroll
    for (int j = 0; j < 8; ++j) h[j] = __float2half_rn(f[j]);
    *(uint4*)(g_xh + i) = *(const uint4*)h;
}

// ---------------- GEMM ----------------

__device__ __forceinline__ uint32_t smem_u32(const void* p) {
    return (uint32_t)__cvta_generic_to_shared(p);
}

__global__ __launch_bounds__(128, 2) void ternary_gemm_kernel(float* __restrict__ out) {
    extern __shared__ char smem[];
    const uint32_t sbase = smem_u32(smem);

    const int tid  = threadIdx.x;
    const int lane = tid & 31;
    const int warp = tid >> 5;          // 4 warps
    const int wm = warp >> 1;           // 2 warps along M (64 rows each)
    const int wn = warp & 1;            // 2 warps along N (64 cols each)
    const int bm = blockIdx.y * BM;
    const int bn = blockIdx.x * BN;

    float acc[4][8][4];                 // fp32 accumulators, 64x64 warp tile
#pragma unroll
    for (int i = 0; i < 4; ++i)
#pragma unroll
        for (int j = 0; j < 8; ++j)
#pragma unroll
            for (int k = 0; k < 4; ++k) acc[i][j][k] = 0.f;

    // cp.async: 128 threads; A and B each 1024 16B-chunks -> 8 per thread each
    auto load_tile = [&](int kt) {
        const uint32_t abase = sbase + (kt % STAGES) * STAGE_BYTES;
        const uint32_t bbase = abase + B_REL;
        const __half* gA = g_xh + (size_t)bm * K_DIM + (size_t)kt * BK;
        const __half* gB = g_ws + (size_t)bn * K_DIM + (size_t)kt * BK;
#pragma unroll
        for (int i = 0; i < 8; ++i) {
            const int idx = tid + i * 128;            // 0..1023
            const int r = idx >> 3;                   // row 0..127
            const int c = idx & 7;
            const uint32_t sw = ((uint32_t)((c ^ r) & 7)) << 4;
            asm volatile("cp.async.cg.shared.global [%0], [%1], 16;"
                         :: "r"(abase + r * 128 + sw),
                            "l"((const char*)(gA + (size_t)r * K_DIM) + c * 16));
            asm volatile("cp.async.cg.shared.global [%0], [%1], 16;"
                         :: "r"(bbase + r * 128 + sw),
                            "l"((const char*)(gB + (size_t)r * K_DIM) + c * 16));
        }
        asm volatile("cp.async.commit_group;");
    };

    auto compute_tile = [&](int kt) {
        const uint32_t abase = sbase + (kt % STAGES) * STAGE_BYTES;
        const uint32_t bbase = abase + B_REL;
#pragma unroll
        for (int ks = 0; ks < 4; ++ks) {
            uint32_t a[4][4];
            uint32_t b[4][4];
            // A: 4 x4-ldmatrix (m16 x k16 tiles)
            {
                const int ch = ks * 2 + (lane >> 4);
#pragma unroll
                for (int mt = 0; mt < 4; ++mt) {
                    const int rr = wm * 64 + mt * 16 + (lane & 15);
                    const uint32_t addr = abase + rr * 128 + (((uint32_t)(ch ^ (rr & 7))) << 4);
                    asm volatile("ldmatrix.sync.aligned.m8n8.x4.shared.b16 {%0,%1,%2,%3}, [%4];"
                                 : "=r"(a[mt][0]), "=r"(a[mt][1]), "=r"(a[mt][2]), "=r"(a[mt][3])
                                 : "r"(addr));
                }
            }
            // B: 4 x4-ldmatrix, each covers 2 n8-tiles (16 B-rows x k16)
            {
                const int ch = ks * 2 + ((lane >> 3) & 1);
#pragma unroll
                for (int p = 0; p < 4; ++p) {
                    const int rr = wn * 64 + p * 16 + (lane & 7) + ((lane >> 4) * 8);
                    const uint32_t addr = bbase + rr * 128 + (((uint32_t)(ch ^ (rr & 7))) << 4);
                    asm volatile("ldmatrix.sync.aligned.m8n8.x4.shared.b16 {%0,%1,%2,%3}, [%4];"
                                 : "=r"(b[p][0]), "=r"(b[p][1]), "=r"(b[p][2]), "=r"(b[p][3])
                                 : "r"(addr));
                }
            }
#pragma unroll
            for (int mt = 0; mt < 4; ++mt)
#pragma unroll
                for (int nt = 0; nt < 8; ++nt) {
                    const int p = nt >> 1, h = (nt & 1) * 2;
                    asm volatile("mma.sync.aligned.m16n8k16.row.col.f32.f16.f16.f32 "
                                 "{%0,%1,%2,%3}, {%4,%5,%6,%7}, {%8,%9}, {%0,%1,%2,%3};"
                                 : "+f"(acc[mt][nt][0]), "+f"(acc[mt][nt][1]),
                                   "+f"(acc[mt][nt][2]), "+f"(acc[mt][nt][3])
                                 : "r"(a[mt][0]), "r"(a[mt][1]), "r"(a[mt][2]), "r"(a[mt][3]),
                                   "r"(b[p][h]), "r"(b[p][h + 1]));
                }
        }
    };

    load_tile(0);
    load_tile(1);

    for (int kt = 0; kt < KTILES; ++kt) {
        asm volatile("cp.async.wait_group %0;" :: "n"(1));
        __syncthreads();                 // stage kt ready; all warps done reading stage kt-1
        if (kt + 2 < KTILES) load_tile(kt + 2);
        compute_tile(kt);
    }

    // epilogue
    const float alpha = g_absum * (1.0f / ((float)N_DIM * (float)K_DIM));
    const int row0 = bm + wm * 64 + (lane >> 2);
    const int col0 = bn + wn * 64 + (lane & 3) * 2;
#pragma unroll
    for (int mt = 0; mt < 4; ++mt) {
        float* o0 = out + (size_t)(row0 + mt * 16) * N_DIM + col0;
        float* o1 = o0 + (size_t)8 * N_DIM;
#pragma unroll
        for (int nt = 0; nt < 8; ++nt) {
            *(float2*)(o0 + nt * 8) = make_float2(alpha * acc[mt][nt][0], alpha * acc[mt][nt][1]);
            *(float2*)(o1 + nt * 8) = make_float2(alpha * acc[mt][nt][2], alpha * acc[mt][nt][3]);
        }
    }
}

// ---------------- launch ----------------

extern "C" void kernel_launch(void* const* d_in, const int* in_sizes, int n_in,
                              void* d_out, int out_size) {
    const float* x = (const float*)d_in[0];
    const float* w = (const float*)d_in[1];
    if (n_in >= 2 && in_sizes[0] < in_sizes[1]) {  // defensive: x is the bigger tensor
        const float* t = x; x = w; w = t;
    }
    float* out = (float*)d_out;

    cudaFuncSetAttribute(ternary_gemm_kernel,
                         cudaFuncAttributeMaxDynamicSharedMemorySize, SMEM_TOTAL);

    zero_sum_kernel<<<1, 1>>>();
    abs_sum_kernel<<<2048, 256>>>(w);
    quantize_w_kernel<<<(N_DIM * (size_t)K_DIM / 8) / 256, 256>>>(w);
    convert_x_kernel<<<((size_t)M_DIM * K_DIM / 8) / 256, 256>>>(x);

    dim3 grid(N_DIM / BN, M_DIM / BM);
    ternary_gemm_kernel<<<grid, 128, SMEM_TOTAL>>>(out);
}

// round 10
// speedup vs baseline: 2.5262x; 1.0472x over previous
#include <cuda_runtime.h>
#include <cuda_fp16.h>
#include <cstdint>

#define M_DIM 8192
#define N_DIM 4096
#define K_DIM 4096

#define BM 128
#define BN 128
#define BK 64
#define STAGES 3
#define KTILES (K_DIM / BK)

// per-stage smem: A 128x64 f16 (16KB) + B 128x64 f16 (16KB) = 32KB; 3 stages = 96KB
#define STAGE_BYTES 32768
#define B_REL 16384
#define SMEM_TOTAL (STAGES * STAGE_BYTES)

// Scratch (static device arrays: allowed; cudaMalloc: not)
__device__ __half g_xh[(size_t)M_DIM * K_DIM];   // 64 MB: x in fp16
__device__ __half g_ws[(size_t)N_DIM * K_DIM];   // 32 MB: ternary sign pattern in fp16
__device__ float  g_absum;

// ---------------- prep kernels ----------------

__global__ void zero_sum_kernel() { g_absum = 0.0f; }

__global__ void abs_sum_kernel(const float* __restrict__ w) {
    const int n4 = (N_DIM * K_DIM) / 4;
    float s = 0.f;
    const float4* w4 = (const float4*)w;
    for (int j = blockIdx.x * blockDim.x + threadIdx.x; j < n4; j += gridDim.x * blockDim.x) {
        float4 v = w4[j];
        s += fabsf(v.x) + fabsf(v.y) + fabsf(v.z) + fabsf(v.w);
    }
#pragma unroll
    for (int o = 16; o; o >>= 1) s += __shfl_xor_sync(0xffffffffu, s, o);
    __shared__ float red[8];
    int lane = threadIdx.x & 31, wid = threadIdx.x >> 5;
    if (lane == 0) red[wid] = s;
    __syncthreads();
    if (wid == 0) {
        s = (lane < 8) ? red[lane] : 0.f;
#pragma unroll
        for (int o = 4; o; o >>= 1) s += __shfl_xor_sync(0xffffffffu, s, o);
        if (lane == 0) atomicAdd(&g_absum, s);
    }
}

__global__ void quantize_w_kernel(const float* __restrict__ w) {
    const float t = 0.5f * g_absum * (1.0f / ((float)N_DIM * (float)K_DIM));
    size_t i = ((size_t)blockIdx.x * blockDim.x + threadIdx.x) * 8;
    float4 v0 = *(const float4*)(w + i);
    float4 v1 = *(const float4*)(w + i + 4);
    float f[8] = {v0.x, v0.y, v0.z, v0.w, v1.x, v1.y, v1.z, v1.w};
    __half h[8];
#pragma unroll
    for (int j = 0; j < 8; ++j)
        h[j] = __float2half_rn(f[j] > t ? 1.0f : (f[j] < -t ? -1.0f : 0.0f));
    *(uint4*)(g_ws + i) = *(const uint4*)h;
}

__global__ void convert_x_kernel(const float* __restrict__ x) {
    size_t i = ((size_t)blockIdx.x * blockDim.x + threadIdx.x) * 8;
    float4 v0 = *(const float4*)(x + i);
    float4 v1 = *(const float4*)(x + i + 4);
    float f[8] = {v0.x, v0.y, v0.z, v0.w, v1.x, v1.y, v1.z, v1.w};
    __half h[8];
#pragma unroll
    for (int j = 0; j < 8; ++j) h[j] = __float2half_rn(f[j]);
    *(uint4*)(g_xh + i) = *(const uint4*)h;
}

// ---------------- GEMM ----------------

__device__ __forceinline__ uint32_t smem_u32(const void* p) {
    return (uint32_t)__cvta_generic_to_shared(p);
}

__global__ __launch_bounds__(128, 2) void ternary_gemm_kernel(float* __restrict__ out) {
    extern __shared__ char smem[];
    const uint32_t sbase = smem_u32(smem);

    const int tid  = threadIdx.x;
    const int lane = tid & 31;
    const int warp = tid >> 5;          // 4 warps
    const int wm = warp >> 1;           // 2 warps along M (64 rows each)
    const int wn = warp & 1;            // 2 warps along N (64 cols each)
    const int bm = blockIdx.y * BM;
    const int bn = blockIdx.x * BN;

    // phase stagger: odd-bid CTAs start half-way through the K tiles (sum order only)
    const int bid = blockIdx.y * gridDim.x + blockIdx.x;
    const int s0  = (bid & 1) * (KTILES / 2);

    float acc[4][8][4];                 // fp32 accumulators, 64x64 warp tile
#pragma unroll
    for (int i = 0; i < 4; ++i)
#pragma unroll
        for (int j = 0; j < 8; ++j)
#pragma unroll
            for (int k = 0; k < 4; ++k) acc[i][j][k] = 0.f;

    // cp.async: 128 threads; A and B each 1024 16B-chunks -> 8 per thread each
    auto load_tile = [&](int seq) {
        const int kt = (seq + s0) & (KTILES - 1);
        const uint32_t abase = sbase + (seq % STAGES) * STAGE_BYTES;
        const uint32_t bbase = abase + B_REL;
        const __half* gA = g_xh + (size_t)bm * K_DIM + (size_t)kt * BK;
        const __half* gB = g_ws + (size_t)bn * K_DIM + (size_t)kt * BK;
#pragma unroll
        for (int i = 0; i < 8; ++i) {
            const int idx = tid + i * 128;            // 0..1023
            const int r = idx >> 3;                   // row 0..127
            const int c = idx & 7;
            const uint32_t sw = ((uint32_t)((c ^ r) & 7)) << 4;
            asm volatile("cp.async.cg.shared.global [%0], [%1], 16;"
                         :: "r"(abase + r * 128 + sw),
                            "l"((const char*)(gA + (size_t)r * K_DIM) + c * 16));
            asm volatile("cp.async.cg.shared.global [%0], [%1], 16;"
                         :: "r"(bbase + r * 128 + sw),
                            "l"((const char*)(gB + (size_t)r * K_DIM) + c * 16));
        }
        asm volatile("cp.async.commit_group;");
    };

    // load A/B ldmatrix fragments for K-slice ks of the stage at abase/bbase
    auto load_frags = [&](uint32_t abase, uint32_t bbase, int ks,
                          uint32_t (&a)[4][4], uint32_t (&b)[4][4]) {
        {
            const int ch = ks * 2 + (lane >> 4);
#pragma unroll
            for (int mt = 0; mt < 4; ++mt) {
                const int rr = wm * 64 + mt * 16 + (lane & 15);
                const uint32_t addr = abase + rr * 128 + (((uint32_t)(ch ^ (rr & 7))) << 4);
                asm volatile("ldmatrix.sync.aligned.m8n8.x4.shared.b16 {%0,%1,%2,%3}, [%4];"
                             : "=r"(a[mt][0]), "=r"(a[mt][1]), "=r"(a[mt][2]), "=r"(a[mt][3])
                             : "r"(addr));
            }
        }
        {
            const int ch = ks * 2 + ((lane >> 3) & 1);
#pragma unroll
            for (int p = 0; p < 4; ++p) {
                const int rr = wn * 64 + p * 16 + (lane & 7) + ((lane >> 4) * 8);
                const uint32_t addr = bbase + rr * 128 + (((uint32_t)(ch ^ (rr & 7))) << 4);
                asm volatile("ldmatrix.sync.aligned.m8n8.x4.shared.b16 {%0,%1,%2,%3}, [%4];"
                             : "=r"(b[p][0]), "=r"(b[p][1]), "=r"(b[p][2]), "=r"(b[p][3])
                             : "r"(addr));
            }
        }
    };

    auto hmma = [&](const uint32_t (&a)[4][4], const uint32_t (&b)[4][4]) {
#pragma unroll
        for (int mt = 0; mt < 4; ++mt)
#pragma unroll
            for (int nt = 0; nt < 8; ++nt) {
                const int p = nt >> 1, h = (nt & 1) * 2;
                asm volatile("mma.sync.aligned.m16n8k16.row.col.f32.f16.f16.f32 "
                             "{%0,%1,%2,%3}, {%4,%5,%6,%7}, {%8,%9}, {%0,%1,%2,%3};"
                             : "+f"(acc[mt][nt][0]), "+f"(acc[mt][nt][1]),
                               "+f"(acc[mt][nt][2]), "+f"(acc[mt][nt][3])
                             : "r"(a[mt][0]), "r"(a[mt][1]), "r"(a[mt][2]), "r"(a[mt][3]),
                               "r"(b[p][h]), "r"(b[p][h + 1]));
            }
    };

    load_tile(0);
    load_tile(1);

    uint32_t A[2][4][4], B[2][4][4];

    for (int seq = 0; seq < KTILES; ++seq) {
        asm volatile("cp.async.wait_group %0;" :: "n"(1));
        __syncthreads();                 // stage seq ready; all warps done reading stage seq-1
        const uint32_t abase = sbase + (seq % STAGES) * STAGE_BYTES;
        const uint32_t bbase = abase + B_REL;

        load_frags(abase, bbase, 0, A[0], B[0]);   // ks=0 frags first (post-barrier latency)
        if (seq + 2 < KTILES) load_tile(seq + 2);  // then async fill of stage seq+2

#pragma unroll
        for (int ks = 0; ks < 4; ++ks) {
            const int cur = ks & 1;
            if (ks < 3) load_frags(abase, bbase, ks + 1, A[cur ^ 1], B[cur ^ 1]);
            hmma(A[cur], B[cur]);
        }
    }

    // epilogue
    const float alpha = g_absum * (1.0f / ((float)N_DIM * (float)K_DIM));
    const int row0 = bm + wm * 64 + (lane >> 2);
    const int col0 = bn + wn * 64 + (lane & 3) * 2;
#pragma unroll
    for (int mt = 0; mt < 4; ++mt) {
        float* o0 = out + (size_t)(row0 + mt * 16) * N_DIM + col0;
        float* o1 = o0 + (size_t)8 * N_DIM;
#pragma unroll
        for (int nt = 0; nt < 8; ++nt) {
            *(float2*)(o0 + nt * 8) = make_float2(alpha * acc[mt][nt][0], alpha * acc[mt][nt][1]);
            *(float2*)(o1 + nt * 8) = make_float2(alpha * acc[mt][nt][2], alpha * acc[mt][nt][3]);
        }
    }
}

// ---------------- launch ----------------

extern "C" void kernel_launch(void* const* d_in, const int* in_sizes, int n_in,
                              void* d_out, int out_size) {
    const float* x = (const float*)d_in[0];
    const float* w = (const float*)d_in[1];
    if (n_in >= 2 && in_sizes[0] < in_sizes[1]) {  // defensive: x is the bigger tensor
        const float* t = x; x = w; w = t;
    }
    float* out = (float*)d_out;

    cudaFuncSetAttribute(ternary_gemm_kernel,
                         cudaFuncAttributeMaxDynamicSharedMemorySize, SMEM_TOTAL);

    zero_sum_kernel<<<1, 1>>>();
    abs_sum_kernel<<<2048, 256>>>(w);
    quantize_w_kernel<<<(N_DIM * (size_t)K_DIM / 8) / 256, 256>>>(w);
    convert_x_kernel<<<((size_t)M_DIM * K_DIM / 8) / 256, 256>>>(x);

    dim3 grid(N_DIM / BN, M_DIM / BM);
    ternary_gemm_kernel<<<grid, 128, SMEM_TOTAL>>>(out);
}

// round 12
// speedup vs baseline: 2.6767x; 1.0596x over previous
#include <cuda_runtime.h>
#include <cuda_fp16.h>
#include <cstdint>

#define M_DIM 8192
#define N_DIM 4096
#define K_DIM 4096

#define BM 128
#define BN 128
#define BK 64
#define STAGES 3
#define KTILES (K_DIM / BK)

// per-stage smem: A 128x64 f16 (16KB) + B 128x64 f16 (16KB) = 32KB; 3 stages = 96KB
#define STAGE_BYTES 32768
#define B_REL 16384
#define SMEM_TOTAL (STAGES * STAGE_BYTES)

// Scratch (static device arrays: allowed; cudaMalloc: not)
__device__ __half g_xh[(size_t)M_DIM * K_DIM];   // 64 MB: x in fp16
__device__ __half g_ws[(size_t)N_DIM * K_DIM];   // 32 MB: ternary sign pattern in fp16
__device__ float  g_absum;

// ---------------- prep kernels ----------------

__global__ void zero_sum_kernel() { g_absum = 0.0f; }

// Fused: convert x (8 elems/thread, exact cover) + abs-sum of W (4 elems/thread)
__global__ void prep_kernel(const float* __restrict__ x, const float* __restrict__ w) {
    const size_t t = (size_t)blockIdx.x * blockDim.x + threadIdx.x;  // 0 .. 4194303

    // x conversion: 8 fp32 -> 8 fp16
    {
        size_t i = t * 8;
        float4 v0 = *(const float4*)(x + i);
        float4 v1 = *(const float4*)(x + i + 4);
        float f[8] = {v0.x, v0.y, v0.z, v0.w, v1.x, v1.y, v1.z, v1.w};
        __half h[8];
#pragma unroll
        for (int j = 0; j < 8; ++j) h[j] = __float2half_rn(f[j]);
        *(uint4*)(g_xh + i) = *(const uint4*)h;
    }

    // |W| partial sum: 4 fp32 per thread (4.19M threads x 4 = 16.7M elems)
    float s = 0.f;
    {
        float4 v = ((const float4*)w)[t];
        s = fabsf(v.x) + fabsf(v.y) + fabsf(v.z) + fabsf(v.w);
    }
#pragma unroll
    for (int o = 16; o; o >>= 1) s += __shfl_xor_sync(0xffffffffu, s, o);
    __shared__ float red[8];
    const int lane = threadIdx.x & 31, wid = threadIdx.x >> 5;
    if (lane == 0) red[wid] = s;
    __syncthreads();
    if (wid == 0) {
        s = (lane < 8) ? red[lane] : 0.f;
#pragma unroll
        for (int o = 4; o; o >>= 1) s += __shfl_xor_sync(0xffffffffu, s, o);
        if (lane == 0) atomicAdd(&g_absum, s);
    }
}

__global__ void quantize_w_kernel(const float* __restrict__ w) {
    const float t = 0.5f * g_absum * (1.0f / ((float)N_DIM * (float)K_DIM));
    size_t i = ((size_t)blockIdx.x * blockDim.x + threadIdx.x) * 8;
    float4 v0 = *(const float4*)(w + i);
    float4 v1 = *(const float4*)(w + i + 4);
    float f[8] = {v0.x, v0.y, v0.z, v0.w, v1.x, v1.y, v1.z, v1.w};
    __half h[8];
#pragma unroll
    for (int j = 0; j < 8; ++j)
        h[j] = __float2half_rn(f[j] > t ? 1.0f : (f[j] < -t ? -1.0f : 0.0f));
    *(uint4*)(g_ws + i) = *(const uint4*)h;
}

// ---------------- GEMM ----------------

__device__ __forceinline__ uint32_t smem_u32(const void* p) {
    return (uint32_t)__cvta_generic_to_shared(p);
}

__global__ __launch_bounds__(128, 2) void ternary_gemm_kernel(float* __restrict__ out) {
    extern __shared__ char smem[];
    const uint32_t sbase = smem_u32(smem);

    const int tid  = threadIdx.x;
    const int lane = tid & 31;
    const int warp = tid >> 5;          // 4 warps
    const int wm = warp >> 1;           // 2 warps along M (64 rows each)
    const int wn = warp & 1;            // 2 warps along N (64 cols each)
    const int bm = blockIdx.y * BM;
    const int bn = blockIdx.x * BN;

    // 4-phase K stagger (sum-order change only): decorrelate co-resident CTAs
    const int bid = blockIdx.y * gridDim.x + blockIdx.x;
    const int s0  = (bid & 3) * (KTILES / 4);

    float acc[4][8][4];                 // fp32 accumulators, 64x64 warp tile
#pragma unroll
    for (int i = 0; i < 4; ++i)
#pragma unroll
        for (int j = 0; j < 8; ++j)
#pragma unroll
            for (int k = 0; k < 4; ++k) acc[i][j][k] = 0.f;

    // precomputed ldmatrix smem offsets (ks=0); addr(ks) = base + (off ^ (ks<<5))
    uint32_t offA[4], offB[4];
    {
        const int chA = lane >> 4;                 // bit0 of chunk
#pragma unroll
        for (int mt = 0; mt < 4; ++mt) {
            const int rr = wm * 64 + mt * 16 + (lane & 15);
            offA[mt] = rr * 128 + (((uint32_t)(chA ^ (rr & 7))) << 4);
        }
        const int chB = (lane >> 3) & 1;
#pragma unroll
        for (int p = 0; p < 4; ++p) {
            const int rr = wn * 64 + p * 16 + (lane & 7) + ((lane >> 4) * 8);
            offB[p] = rr * 128 + (((uint32_t)(chB ^ (rr & 7))) << 4);
        }
    }

    // cp.async: 128 threads; A and B each 1024 16B-chunks -> 8 per thread each
    auto load_tile = [&](int seq) {
        const int kt = (seq + s0) & (KTILES - 1);
        const uint32_t abase = sbase + (seq % STAGES) * STAGE_BYTES;
        const uint32_t bbase = abase + B_REL;
        const __half* gA = g_xh + (size_t)bm * K_DIM + (size_t)kt * BK;
        const __half* gB = g_ws + (size_t)bn * K_DIM + (size_t)kt * BK;
#pragma unroll
        for (int i = 0; i < 8; ++i) {
            const int idx = tid + i * 128;            // 0..1023
            const int r = idx >> 3;                   // row 0..127
            const int c = idx & 7;
            const uint32_t sw = ((uint32_t)((c ^ r) & 7)) << 4;
            asm volatile("cp.async.cg.shared.global [%0], [%1], 16;"
                         :: "r"(abase + r * 128 + sw),
                            "l"((const char*)(gA + (size_t)r * K_DIM) + c * 16));
            asm volatile("cp.async.cg.shared.global [%0], [%1], 16;"
                         :: "r"(bbase + r * 128 + sw),
                            "l"((const char*)(gB + (size_t)r * K_DIM) + c * 16));
        }
        asm volatile("cp.async.commit_group;");
    };

    // load A/B ldmatrix fragments for K-slice ks of the stage at abase/bbase
    auto load_frags = [&](uint32_t abase, uint32_t bbase, int ks,
                          uint32_t (&a)[4][4], uint32_t (&b)[4][4]) {
        const uint32_t kx = (uint32_t)ks << 5;
#pragma unroll
        for (int mt = 0; mt < 4; ++mt) {
            const uint32_t addr = abase + (offA[mt] ^ kx);
            asm volatile("ldmatrix.sync.aligned.m8n8.x4.shared.b16 {%0,%1,%2,%3}, [%4];"
                         : "=r"(a[mt][0]), "=r"(a[mt][1]), "=r"(a[mt][2]), "=r"(a[mt][3])
                         : "r"(addr));
        }
#pragma unroll
        for (int p = 0; p < 4; ++p) {
            const uint32_t addr = bbase + (offB[p] ^ kx);
            asm volatile("ldmatrix.sync.aligned.m8n8.x4.shared.b16 {%0,%1,%2,%3}, [%4];"
                         : "=r"(b[p][0]), "=r"(b[p][1]), "=r"(b[p][2]), "=r"(b[p][3])
                         : "r"(addr));
        }
    };

    auto hmma = [&](const uint32_t (&a)[4][4], const uint32_t (&b)[4][4]) {
#pragma unroll
        for (int mt = 0; mt < 4; ++mt)
#pragma unroll
            for (int nt = 0; nt < 8; ++nt) {
                const int p = nt >> 1, h = (nt & 1) * 2;
                asm volatile("mma.sync.aligned.m16n8k16.row.col.f32.f16.f16.f32 "
                             "{%0,%1,%2,%3}, {%4,%5,%6,%7}, {%8,%9}, {%0,%1,%2,%3};"
                             : "+f"(acc[mt][nt][0]), "+f"(acc[mt][nt][1]),
                               "+f"(acc[mt][nt][2]), "+f"(acc[mt][nt][3])
                             : "r"(a[mt][0]), "r"(a[mt][1]), "r"(a[mt][2]), "r"(a[mt][3]),
                               "r"(b[p][h]), "r"(b[p][h + 1]));
            }
    };

    load_tile(0);
    load_tile(1);

    uint32_t A[2][4][4], B[2][4][4];

    for (int seq = 0; seq < KTILES; ++seq) {
        asm volatile("cp.async.wait_group %0;" :: "n"(1));
        __syncthreads();                 // stage seq ready; all warps done reading stage seq-1
        const uint32_t abase = sbase + (seq % STAGES) * STAGE_BYTES;
        const uint32_t bbase = abase + B_REL;

        load_frags(abase, bbase, 0, A[0], B[0]);   // ks=0 frags first (post-barrier latency)
        if (seq + 2 < KTILES) load_tile(seq + 2);  // then async fill of stage seq+2

#pragma unroll
        for (int ks = 0; ks < 4; ++ks) {
            const int cur = ks & 1;
            if (ks < 3) load_frags(abase, bbase, ks + 1, A[cur ^ 1], B[cur ^ 1]);
            hmma(A[cur], B[cur]);
        }
    }

    // epilogue
    const float alpha = g_absum * (1.0f / ((float)N_DIM * (float)K_DIM));
    const int row0 = bm + wm * 64 + (lane >> 2);
    const int col0 = bn + wn * 64 + (lane & 3) * 2;
#pragma unroll
    for (int mt = 0; mt < 4; ++mt) {
        float* o0 = out + (size_t)(row0 + mt * 16) * N_DIM + col0;
        float* o1 = o0 + (size_t)8 * N_DIM;
#pragma unroll
        for (int nt = 0; nt < 8; ++nt) {
            *(float2*)(o0 + nt * 8) = make_float2(alpha * acc[mt][nt][0], alpha * acc[mt][nt][1]);
            *(float2*)(o1 + nt * 8) = make_float2(alpha * acc[mt][nt][2], alpha * acc[mt][nt][3]);
        }
    }
}

// ---------------- launch ----------------

extern "C" void kernel_launch(void* const* d_in, const int* in_sizes, int n_in,
                              void* d_out, int out_size) {
    const float* x = (const float*)d_in[0];
    const float* w = (const float*)d_in[1];
    if (n_in >= 2 && in_sizes[0] < in_sizes[1]) {  // defensive: x is the bigger tensor
        const float* t = x; x = w; w = t;
    }
    float* out = (float*)d_out;

    cudaFuncSetAttribute(ternary_gemm_kernel,
                         cudaFuncAttributeMaxDynamicSharedMemorySize, SMEM_TOTAL);

    zero_sum_kernel<<<1, 1>>>();
    prep_kernel<<<16384, 256>>>(x, w);   // x->fp16 convert + |W| sum, fused
    quantize_w_kernel<<<(N_DIM * (size_t)K_DIM / 8) / 256, 256>>>(w);

    dim3 grid(N_DIM / BN, M_DIM / BM);
    ternary_gemm_kernel<<<grid, 128, SMEM_TOTAL>>>(out);
}